// round 9
// baseline (speedup 1.0000x reference)
#include <cuda_runtime.h>
#include <cstdint>

typedef unsigned long long ull;

#define HH 192
#define WW 192
#define HWSZ 36864
#define CHW (64*36864)
#define BB 4

// ---------- f32x2 helpers (Blackwell dual-rate fp32) ----------
__device__ __forceinline__ ull fma2(ull a, ull b, ull c) {
    ull d;
    asm("fma.rn.f32x2 %0, %1, %2, %3;" : "=l"(d) : "l"(a), "l"(b), "l"(c));
    return d;
}
__device__ __forceinline__ ull pack2(float lo, float hi) {
    ull r; asm("mov.b64 %0, {%1, %2};" : "=l"(r) : "f"(lo), "f"(hi)); return r;
}
__device__ __forceinline__ void unpack2(ull v, float& lo, float& hi) {
    asm("mov.b64 {%0, %1}, %2;" : "=f"(lo), "=f"(hi) : "l"(v));
}

// ---------- scratch (no cudaMalloc allowed) ----------
__device__ __align__(16) float g_x1[BB*CHW];
__device__ __align__(16) float g_x2[BB*CHW];
__device__ __align__(16) float g_tmp[BB*CHW];
__device__ __align__(16) float g_off[BB*98*HWSZ];
__device__ __align__(16) float g_wT[300000];      // conv weights [ic][k][o]
__device__ __align__(16) ull   g_wdup[83*4096];   // deform weights [k][c][o] as dup f32x2
__device__ __align__(16) float g_wpk_in[64*128];
__device__ __align__(16) float g_wpk_out[64*64];

// ---------- weight transposes ----------
__global__ void k_tr_deform_dup(const float* __restrict__ w, ull* __restrict__ o, int KK) {
    int idx = blockIdx.x*256 + threadIdx.x;
    if (idx >= KK*4096) return;
    int oo = idx & 63, c = (idx >> 6) & 63, k = idx >> 12;
    float v = w[(oo*64 + c)*KK + k];       // out[k][c][o], duplicated
    o[idx] = pack2(v, v);
}
__global__ void k_tr_conv(const float* __restrict__ w, float* __restrict__ o, int O, int KK) {
    int idx = blockIdx.x*256 + threadIdx.x;
    if (idx >= 64*KK*O) return;
    int oo = idx % O;
    int rem = idx / O;
    int k = rem % KK;
    int ic = rem / KK;
    o[idx] = w[(oo*64 + ic)*KK + k];       // out[ic][k][o]
}
__global__ void k_tr_lin(const float* __restrict__ w, float* __restrict__ o, int O, int C) {
    int idx = blockIdx.x*256 + threadIdx.x;
    if (idx >= O*C) return;
    int oo = idx % O, c = idx / O;
    o[idx] = w[oo*C + c];                  // out[c][o]
}

// ---------- LayerNorm(channel) + 1x1 conv to 128ch, split x1/x2 ----------
__global__ __launch_bounds__(128) void k_ln_win(
    const float* __restrict__ x, const float* __restrict__ lnw,
    const float* __restrict__ lnb, const float* __restrict__ wpk,
    const float* __restrict__ bin,
    float* __restrict__ x1, float* __restrict__ x2) {
    __shared__ ull sW[4096];
    __shared__ float sLW[64], sLB[64], sB[128];
    int t = threadIdx.x;
    const ull* wp = (const ull*)wpk;
    #pragma unroll
    for (int i = 0; i < 32; i++) sW[t + i*128] = wp[t + i*128];
    if (t < 64) { sLW[t] = lnw[t]; sLB[t] = lnb[t]; }
    sB[t] = bin[t];
    __syncthreads();
    int pix = blockIdx.x*128 + t;
    int b = pix / HWSZ, hw = pix - b*HWSZ;
    const float* xp = x + b*CHW + hw;
    float sum = 0.f, sq = 0.f;
    for (int c = 0; c < 64; c++) {
        float v = __ldg(xp + c*HWSZ);
        sum += v; sq += v*v;
    }
    float mu  = sum * 0.015625f;
    float var = sq * 0.015625f - mu*mu;
    float inv = rsqrtf(var + 1e-5f);
    #pragma unroll 1
    for (int half = 0; half < 2; half++) {
        ull acc[32];
        #pragma unroll
        for (int j = 0; j < 32; j++) acc[j] = pack2(sB[half*64+2*j], sB[half*64+2*j+1]);
        #pragma unroll 1
        for (int c = 0; c < 64; c++) {
            float v = __ldg(xp + c*HWSZ);
            v = (v - mu)*inv*sLW[c] + sLB[c];
            ull vb = pack2(v, v);
            const ull* wr = sW + c*64 + half*32;
            #pragma unroll
            for (int j = 0; j < 32; j++) acc[j] = fma2(vb, wr[j], acc[j]);
        }
        float* op = (half ? x2 : x1) + b*CHW + hw;
        #pragma unroll
        for (int j = 0; j < 32; j++) {
            float lo, hi; unpack2(acc[j], lo, hi);
            op[(2*j)*HWSZ] = lo; op[(2*j+1)*HWSZ] = hi;
        }
    }
}

// ---------- direct conv (offset branches): 32x32 tile, 2x2 px/thread, 16 oc ----------
template<int K, int OTOT>
__global__ __launch_bounds__(256) void k_conv(
    const float* __restrict__ src, const float* __restrict__ owT,
    const float* __restrict__ bias, float* __restrict__ dst) {
    constexpr int PAD = K/2;
    constexpr int KK  = K*K;
    constexpr int TIW = 32 + K - 1;
    constexpr int OG  = (OTOT + 15)/16;
    __shared__ float sIn[4*TIW*TIW];
    __shared__ ull   sW[4*KK*8];
    int t  = threadIdx.x;
    int tx = t & 15, ty = t >> 4;
    int bz = blockIdx.z;
    int og = bz % OG;
    int b  = bz / OG;
    int oc0 = og*16;
    int ox0 = blockIdx.x*32, oy0 = blockIdx.y*32;
    int gx0 = ox0 - PAD, gy0 = oy0 - PAD;
    const float* sb = src + b*CHW;
    ull acc[2][2][8];
    #pragma unroll
    for (int dy = 0; dy < 2; dy++)
    #pragma unroll
    for (int dx = 0; dx < 2; dx++)
    #pragma unroll
    for (int j = 0; j < 8; j++) acc[dy][dx][j] = 0ULL;

    #pragma unroll 1
    for (int ic0 = 0; ic0 < 64; ic0 += 4) {
        __syncthreads();
        for (int i = t; i < 4*TIW*TIW; i += 256) {
            int ic = i / (TIW*TIW);
            int r  = i - ic*TIW*TIW;
            int yy = r / TIW, xx = r - yy*TIW;
            int gy = gy0 + yy, gx = gx0 + xx;
            float v = 0.f;
            if (gy >= 0 && gy < HH && gx >= 0 && gx < WW)
                v = __ldg(sb + (ic0+ic)*HWSZ + gy*WW + gx);
            sIn[i] = v;
        }
        for (int i = t; i < 4*KK*8; i += 256) {
            int j  = i & 7;
            int rem = i >> 3;
            int k  = rem % KK;
            int ic = rem / KK;
            int oc = oc0 + 2*j;
            ull v = 0ULL;
            if (oc < OTOT)
                v = *(const ull*)(owT + (size_t)((ic0+ic)*KK + k)*OTOT + oc);
            sW[i] = v;
        }
        __syncthreads();
        #pragma unroll 1
        for (int ic = 0; ic < 4; ic++) {
            #pragma unroll 1
            for (int ky = 0; ky < K; ky++) {
                #pragma unroll
                for (int kx = 0; kx < K; kx++) {
                    ull v2[2][2];
                    #pragma unroll
                    for (int dy = 0; dy < 2; dy++)
                    #pragma unroll
                    for (int dx = 0; dx < 2; dx++) {
                        float f = sIn[ic*TIW*TIW + (2*ty+ky+dy)*TIW + 2*tx+kx+dx];
                        v2[dy][dx] = pack2(f, f);
                    }
                    const ull* wr = sW + (ic*KK + ky*K + kx)*8;
                    #pragma unroll
                    for (int j = 0; j < 8; j++) {
                        ull wv = wr[j];
                        acc[0][0][j] = fma2(v2[0][0], wv, acc[0][0][j]);
                        acc[0][1][j] = fma2(v2[0][1], wv, acc[0][1][j]);
                        acc[1][0][j] = fma2(v2[1][0], wv, acc[1][0][j]);
                        acc[1][1][j] = fma2(v2[1][1], wv, acc[1][1][j]);
                    }
                }
            }
        }
    }
    #pragma unroll
    for (int j = 0; j < 8; j++) {
        int oc = oc0 + 2*j;
        if (oc < OTOT) {
            float b0 = __ldg(bias + oc), b1 = __ldg(bias + oc + 1);
            #pragma unroll
            for (int dy = 0; dy < 2; dy++)
            #pragma unroll
            for (int dx = 0; dx < 2; dx++) {
                float lo, hi; unpack2(acc[dy][dx][j], lo, hi);
                int py = oy0 + 2*ty + dy, px = ox0 + 2*tx + dx;
                float* dp = dst + (size_t)b*OTOT*HWSZ + oc*HWSZ + py*WW + px;
                dp[0]    = lo + b0;
                dp[HWSZ] = hi + b1;
            }
        }
    }
}

// ---------- deformable conv v2b: register coords + pre-dup weights + offset prefetch ----------
// Block: 256 threads, tile = 128 px x 64 oc, K-loop over 64 channels per tap.
// smem: dup weights 32KB + samples 32KB = 64KB -> 3 CTAs/SM. 2 syncs/tap.
template<int K, int PAD>
__global__ __launch_bounds__(256) void k_deform2b(
    const float* __restrict__ src, const float* __restrict__ off,
    const ull* __restrict__ wdup, const float* __restrict__ bias,
    float* __restrict__ dst) {
    constexpr int KK = K*K;
    extern __shared__ char smem[];
    ull*   sWd = (ull*)smem;                  // [c][64 oc] dup f32x2, 32768B
    float* sS  = (float*)(smem + 32768);      // [c][128 px], 32768B

    int t = threadIdx.x;
    int hw0 = blockIdx.x * 128;
    int b   = blockIdx.y;
    const float* srcb = src + b*CHW;
    const float* offb = off + (size_t)b*(2*KK)*HWSZ;

    int px_t = t & 31;        // pixel group (4 px) for GEMM
    int oc_t = t >> 5;        // oc group (8 oc) -- uniform per warp
    int spx  = t & 127;       // sampling pixel
    int c0   = (t >> 7) * 32; // sampling channel base

    int hw = hw0 + spx;
    int hh = hw / WW, xx = hw - hh*WW;

    ull acc[2][8];
    #pragma unroll
    for (int pp = 0; pp < 2; pp++)
    #pragma unroll
    for (int j = 0; j < 8; j++) acc[pp][j] = 0ULL;

    // prefetch tap-0 offsets
    float oy = __ldg(offb + hw);
    float ox = __ldg(offb + HWSZ + hw);

    #pragma unroll 1
    for (int k = 0; k < KK; k++) {
        // --- coords in registers (redundant per thread-pair; no smem stage) ---
        float w0, w1, w2, w3;
        int   o0, o1, o2, o3;
        {
            int ki = k / K, kj = k - ki*K;
            float py = (float)(hh + ki - PAD) + oy;
            float px = (float)(xx + kj - PAD) + ox;
            float y0f = floorf(py), x0f = floorf(px);
            float wy = py - y0f, wx = px - x0f;
            int y0 = (int)y0f, x0 = (int)x0f;
            int y1 = y0 + 1, x1i = x0 + 1;
            float my0 = (y0  >= 0 && y0  < HH) ? 1.f : 0.f;
            float my1 = (y1  >= 0 && y1  < HH) ? 1.f : 0.f;
            float mx0 = (x0  >= 0 && x0  < WW) ? 1.f : 0.f;
            float mx1 = (x1i >= 0 && x1i < WW) ? 1.f : 0.f;
            int yc0 = min(max(y0, 0), HH-1), yc1 = min(max(y1, 0), HH-1);
            int xc0 = min(max(x0, 0), WW-1), xc1 = min(max(x1i, 0), WW-1);
            w0 = my0*mx0*(1.f-wy)*(1.f-wx);
            w1 = my0*mx1*(1.f-wy)*wx;
            w2 = my1*mx0*wy*(1.f-wx);
            w3 = my1*mx1*wy*wx;
            o0 = yc0*WW + xc0;
            o1 = yc0*WW + xc1;
            o2 = yc1*WW + xc0;
            o3 = yc1*WW + xc1;
        }
        // --- stage weights: straight 32KB copy of pre-duplicated pairs ---
        {
            const uint4* wg = (const uint4*)(wdup + (size_t)k*4096);
            uint4* sw4 = (uint4*)sWd;
            #pragma unroll
            for (int i = 0; i < 8; i++)
                sw4[t + i*256] = __ldg(wg + t + i*256);
        }
        // --- sampling: 32 channels for pixel spx ---
        {
            const float* sp0 = srcb + (size_t)c0*HWSZ;
            #pragma unroll 4
            for (int i = 0; i < 32; i++) {
                const float* p = sp0 + (size_t)i*HWSZ;
                float v = __ldg(p+o0)*w0 + __ldg(p+o1)*w1
                        + __ldg(p+o2)*w2 + __ldg(p+o3)*w3;
                sS[(c0+i)*128 + spx] = v;
            }
        }
        __syncthreads();
        // --- prefetch next tap's offsets (latency hidden under GEMM) ---
        if (k + 1 < KK) {
            oy = __ldg(offb + (size_t)(2*k+2)*HWSZ + hw);
            ox = __ldg(offb + (size_t)(2*k+3)*HWSZ + hw);
        }
        // --- GEMM: 64 c iters, 5 LDS.128 + 16 fma2 each ---
        {
            const float* sSp = sS + px_t*4;
            const ulonglong2* wp2 = (const ulonglong2*)(sWd + oc_t*8);
            #pragma unroll 4
            for (int c = 0; c < 64; c++) {
                ulonglong2 sv = *(const ulonglong2*)(sSp + c*128);
                ulonglong2 w01 = wp2[c*32 + 0];
                ulonglong2 w23 = wp2[c*32 + 1];
                ulonglong2 w45 = wp2[c*32 + 2];
                ulonglong2 w67 = wp2[c*32 + 3];
                acc[0][0] = fma2(sv.x, w01.x, acc[0][0]);
                acc[1][0] = fma2(sv.y, w01.x, acc[1][0]);
                acc[0][1] = fma2(sv.x, w01.y, acc[0][1]);
                acc[1][1] = fma2(sv.y, w01.y, acc[1][1]);
                acc[0][2] = fma2(sv.x, w23.x, acc[0][2]);
                acc[1][2] = fma2(sv.y, w23.x, acc[1][2]);
                acc[0][3] = fma2(sv.x, w23.y, acc[0][3]);
                acc[1][3] = fma2(sv.y, w23.y, acc[1][3]);
                acc[0][4] = fma2(sv.x, w45.x, acc[0][4]);
                acc[1][4] = fma2(sv.y, w45.x, acc[1][4]);
                acc[0][5] = fma2(sv.x, w45.y, acc[0][5]);
                acc[1][5] = fma2(sv.y, w45.y, acc[1][5]);
                acc[0][6] = fma2(sv.x, w67.x, acc[0][6]);
                acc[1][6] = fma2(sv.y, w67.x, acc[1][6]);
                acc[0][7] = fma2(sv.x, w67.y, acc[0][7]);
                acc[1][7] = fma2(sv.y, w67.y, acc[1][7]);
            }
        }
        __syncthreads();
    }
    // --- epilogue: bias + store ---
    float* db = dst + b*CHW;
    #pragma unroll
    for (int pp = 0; pp < 2; pp++) {
        int hws = hw0 + px_t*4 + pp*2;
        #pragma unroll
        for (int j = 0; j < 8; j++) {
            int oc = oc_t*8 + j;
            float lo, hi; unpack2(acc[pp][j], lo, hi);
            float bb = __ldg(bias + oc);
            *(float2*)(db + (size_t)oc*HWSZ + hws) = make_float2(lo + bb, hi + bb);
        }
    }
}

// ---------- final: (x1+x2) @ w_out + b_out + residual ----------
__global__ __launch_bounds__(128) void k_final(
    const float* __restrict__ t1, const float* __restrict__ t2,
    const float* __restrict__ xres, const float* __restrict__ wpk,
    const float* __restrict__ bout, float* __restrict__ out) {
    __shared__ ull sW[2048];
    __shared__ float sB[64];
    int t = threadIdx.x;
    const ull* wp = (const ull*)wpk;
    #pragma unroll
    for (int i = 0; i < 16; i++) sW[t + i*128] = wp[t + i*128];
    if (t < 64) sB[t] = bout[t];
    __syncthreads();
    int pix = blockIdx.x*128 + t;
    int b = pix / HWSZ, hw = pix - b*HWSZ;
    const float* p1 = t1 + b*CHW + hw;
    const float* p2 = t2 + b*CHW + hw;
    ull acc[32];
    #pragma unroll
    for (int j = 0; j < 32; j++) acc[j] = pack2(sB[2*j], sB[2*j+1]);
    #pragma unroll 1
    for (int c = 0; c < 64; c++) {
        float v = __ldg(p1 + c*HWSZ) + __ldg(p2 + c*HWSZ);
        ull vb = pack2(v, v);
        const ull* wc = sW + c*32;
        #pragma unroll
        for (int j = 0; j < 32; j++) acc[j] = fma2(vb, wc[j], acc[j]);
    }
    const float* xr = xres + b*CHW + hw;
    float* op = out + b*CHW + hw;
    #pragma unroll
    for (int j = 0; j < 32; j++) {
        float lo, hi; unpack2(acc[j], lo, hi);
        op[(2*j)*HWSZ]   = lo + __ldg(xr + (2*j)*HWSZ);
        op[(2*j+1)*HWSZ] = hi + __ldg(xr + (2*j+1)*HWSZ);
    }
}

extern "C" void kernel_launch(void* const* d_in, const int* in_sizes, int n_in,
                              void* d_out, int out_size) {
    const float* x    = (const float*)d_in[0];
    const float* lnw  = (const float*)d_in[1];
    const float* lnb  = (const float*)d_in[2];
    const float* w_in = (const float*)d_in[3];
    const float* b_in = (const float*)d_in[4];
    const float* w_out= (const float*)d_in[5];
    const float* b_out= (const float*)d_in[6];
    const float* dw1  = (const float*)d_in[7];
    const float* db1  = (const float*)d_in[8];
    const float* dw2  = (const float*)d_in[9];
    const float* db2  = (const float*)d_in[10];
    const float* dw3  = (const float*)d_in[11];
    const float* db3  = (const float*)d_in[12];
    const float* ow1  = (const float*)d_in[13];
    const float* ob1  = (const float*)d_in[14];
    const float* ow2  = (const float*)d_in[15];
    const float* ob2  = (const float*)d_in[16];
    const float* ow3  = (const float*)d_in[17];
    const float* ob3  = (const float*)d_in[18];
    float* out = (float*)d_out;

    float *x1, *x2, *tmp, *offb, *wT, *wpi, *wpo;
    ull *wdup;
    cudaGetSymbolAddress((void**)&x1,  g_x1);
    cudaGetSymbolAddress((void**)&x2,  g_x2);
    cudaGetSymbolAddress((void**)&tmp, g_tmp);
    cudaGetSymbolAddress((void**)&offb,g_off);
    cudaGetSymbolAddress((void**)&wT,  g_wT);
    cudaGetSymbolAddress((void**)&wdup,g_wdup);
    cudaGetSymbolAddress((void**)&wpi, g_wpk_in);
    cudaGetSymbolAddress((void**)&wpo, g_wpk_out);

    const int SMEM_DEF = 65536;
    cudaFuncSetAttribute(k_deform2b<7,3>, cudaFuncAttributeMaxDynamicSharedMemorySize, SMEM_DEF);
    cudaFuncSetAttribute(k_deform2b<5,2>, cudaFuncAttributeMaxDynamicSharedMemorySize, SMEM_DEF);
    cudaFuncSetAttribute(k_deform2b<3,1>, cudaFuncAttributeMaxDynamicSharedMemorySize, SMEM_DEF);

    const int WD1 = 0, WD2 = 49*4096, WD3 = 74*4096;
    const int WO1 = 0;
    const int WO2 = WO1 + 64*25*98;
    const int WO3 = WO2 + 64*25*50;

    // launch order keeps ncu's fixed "-s 5" on k_conv<5,98>
    k_tr_lin<<<(64*128+255)/256, 256>>>(w_in,  wpi, 128, 64);                    // 0
    k_tr_conv<<<(64*25*98+255)/256, 256>>>(ow1, wT+WO1, 98, 25);                 // 1
    k_tr_deform_dup<<<(49*4096+255)/256, 256>>>(dw1, wdup+WD1, 49);              // 2
    k_ln_win<<<BB*HWSZ/128, 128>>>(x, lnw, lnb, wpi, b_in, x1, x2);              // 3
    k_tr_lin<<<(64*64+255)/256, 256>>>(w_out, wpo, 64, 64);                      // 4
    k_conv<5,98><<<dim3(6,6,4*7), 256>>>(x1,  wT+WO1, ob1, offb);                // 5 <- profiled
    k_deform2b<7,3><<<dim3(288,4), 256, SMEM_DEF>>>(x1,  offb, wdup+WD1, db1, tmp);   // 6
    k_tr_conv<<<(64*25*50+255)/256, 256>>>(ow2, wT+WO2, 50, 25);                 // 7
    k_conv<5,50><<<dim3(6,6,4*4), 256>>>(tmp, wT+WO2, ob2, offb);                // 8
    k_tr_deform_dup<<<(25*4096+255)/256, 256>>>(dw2, wdup+WD2, 25);              // 9
    k_deform2b<5,2><<<dim3(288,4), 256, SMEM_DEF>>>(tmp, offb, wdup+WD2, db2, x1);    // 10
    k_tr_conv<<<(64*9*18+255)/256, 256>>>(ow3, wT+WO3, 18, 9);                   // 11
    k_conv<3,18><<<dim3(6,6,4*2), 256>>>(x1,  wT+WO3, ob3, offb);                // 12
    k_tr_deform_dup<<<( 9*4096+255)/256, 256>>>(dw3, wdup+WD3, 9);               // 13
    k_deform2b<3,1><<<dim3(288,4), 256, SMEM_DEF>>>(x1,  offb, wdup+WD3, db3, tmp);   // 14
    k_final<<<BB*HWSZ/128, 128>>>(tmp, x2, x, wpo, b_out, out);                  // 15
}

// round 14
// speedup vs baseline: 1.3253x; 1.3253x over previous
#include <cuda_runtime.h>
#include <cuda_fp16.h>
#include <cstdint>

typedef unsigned long long ull;

#define HH 192
#define WW 192
#define HWSZ 36864
#define CHW (64*36864)
#define BB 4

// ---------- f32x2 helpers (compiles to 2xFFMA on sm_103; used by non-deform kernels) ----------
__device__ __forceinline__ ull fma2(ull a, ull b, ull c) {
    ull d;
    asm("fma.rn.f32x2 %0, %1, %2, %3;" : "=l"(d) : "l"(a), "l"(b), "l"(c));
    return d;
}
__device__ __forceinline__ ull pack2(float lo, float hi) {
    ull r; asm("mov.b64 %0, {%1, %2};" : "=l"(r) : "f"(lo), "f"(hi)); return r;
}
__device__ __forceinline__ void unpack2(ull v, float& lo, float& hi) {
    asm("mov.b64 {%0, %1}, %2;" : "=f"(lo), "=f"(hi) : "l"(v));
}

// ---------- HMMA helper: f16 inputs, f32 accum (sm_80 baseline PTX) ----------
__device__ __forceinline__ void mma_f16(float* d, uint32_t a0, uint32_t a1, uint32_t a2, uint32_t a3,
                                        uint32_t b0, uint32_t b1) {
    asm volatile("mma.sync.aligned.m16n8k16.row.col.f32.f16.f16.f32 "
        "{%0,%1,%2,%3}, {%4,%5,%6,%7}, {%8,%9}, {%0,%1,%2,%3};"
        : "+f"(d[0]), "+f"(d[1]), "+f"(d[2]), "+f"(d[3])
        : "r"(a0), "r"(a1), "r"(a2), "r"(a3), "r"(b0), "r"(b1));
}
__device__ __forceinline__ uint32_t hfu(__half h) {
    return (uint32_t)__half_as_ushort(h);
}

// ---------- scratch ----------
__device__ __align__(16) float g_x1[BB*CHW];
__device__ __align__(16) float g_x2[BB*CHW];
__device__ __align__(16) float g_tmp[BB*CHW];
__device__ __align__(16) float g_off[BB*98*HWSZ];
__device__ __align__(16) float g_wT[300000];        // conv weights [ic][k][o]
__device__ __align__(16) __half g_whfh[83*4096];    // deform weights hi [k][oc][c]
__device__ __align__(16) __half g_whfl[83*4096];    // deform weights lo
__device__ __align__(16) float g_wpk_in[64*128];
__device__ __align__(16) float g_wpk_out[64*64];

// ---------- weight transposes ----------
__global__ void k_tr_deform_hf(const float* __restrict__ w,
                               __half* __restrict__ oh,
                               __half* __restrict__ ol, int KK) {
    int idx = blockIdx.x*256 + threadIdx.x;
    if (idx >= KK*4096) return;
    int c = idx & 63, oc = (idx >> 6) & 63, k = idx >> 12;
    float v = w[(oc*64 + c)*KK + k];           // out[k][oc][c]
    __half h = __float2half_rn(v);
    float r = v - __half2float(h);
    oh[idx] = h;
    ol[idx] = __float2half_rn(r);
}
__global__ void k_tr_conv(const float* __restrict__ w, float* __restrict__ o, int O, int KK) {
    int idx = blockIdx.x*256 + threadIdx.x;
    if (idx >= 64*KK*O) return;
    int oo = idx % O;
    int rem = idx / O;
    int k = rem % KK;
    int ic = rem / KK;
    o[idx] = w[(oo*64 + ic)*KK + k];           // out[ic][k][o]
}
__global__ void k_tr_lin(const float* __restrict__ w, float* __restrict__ o, int O, int C) {
    int idx = blockIdx.x*256 + threadIdx.x;
    if (idx >= O*C) return;
    int oo = idx % O, c = idx / O;
    o[idx] = w[oo*C + c];                      // out[c][o]
}

// ---------- LayerNorm + 1x1 conv to 128ch, split x1/x2 ----------
__global__ __launch_bounds__(128) void k_ln_win(
    const float* __restrict__ x, const float* __restrict__ lnw,
    const float* __restrict__ lnb, const float* __restrict__ wpk,
    const float* __restrict__ bin,
    float* __restrict__ x1, float* __restrict__ x2) {
    __shared__ ull sW[4096];
    __shared__ float sLW[64], sLB[64], sB[128];
    int t = threadIdx.x;
    const ull* wp = (const ull*)wpk;
    #pragma unroll
    for (int i = 0; i < 32; i++) sW[t + i*128] = wp[t + i*128];
    if (t < 64) { sLW[t] = lnw[t]; sLB[t] = lnb[t]; }
    sB[t] = bin[t];
    __syncthreads();
    int pix = blockIdx.x*128 + t;
    int b = pix / HWSZ, hw = pix - b*HWSZ;
    const float* xp = x + b*CHW + hw;
    float sum = 0.f, sq = 0.f;
    for (int c = 0; c < 64; c++) {
        float v = __ldg(xp + c*HWSZ);
        sum += v; sq += v*v;
    }
    float mu  = sum * 0.015625f;
    float var = sq * 0.015625f - mu*mu;
    float inv = rsqrtf(var + 1e-5f);
    #pragma unroll 1
    for (int half = 0; half < 2; half++) {
        ull acc[32];
        #pragma unroll
        for (int j = 0; j < 32; j++) acc[j] = pack2(sB[half*64+2*j], sB[half*64+2*j+1]);
        #pragma unroll 1
        for (int c = 0; c < 64; c++) {
            float v = __ldg(xp + c*HWSZ);
            v = (v - mu)*inv*sLW[c] + sLB[c];
            ull vb = pack2(v, v);
            const ull* wr = sW + c*64 + half*32;
            #pragma unroll
            for (int j = 0; j < 32; j++) acc[j] = fma2(vb, wr[j], acc[j]);
        }
        float* op = (half ? x2 : x1) + b*CHW + hw;
        #pragma unroll
        for (int j = 0; j < 32; j++) {
            float lo, hi; unpack2(acc[j], lo, hi);
            op[(2*j)*HWSZ] = lo; op[(2*j+1)*HWSZ] = hi;
        }
    }
}

// ---------- direct conv (offset branches), FFMA path ----------
template<int K, int OTOT>
__global__ __launch_bounds__(256) void k_conv(
    const float* __restrict__ src, const float* __restrict__ owT,
    const float* __restrict__ bias, float* __restrict__ dst) {
    constexpr int PAD = K/2;
    constexpr int KK  = K*K;
    constexpr int TIW = 32 + K - 1;
    constexpr int OG  = (OTOT + 15)/16;
    __shared__ float sIn[4*TIW*TIW];
    __shared__ ull   sW[4*KK*8];
    int t  = threadIdx.x;
    int tx = t & 15, ty = t >> 4;
    int bz = blockIdx.z;
    int og = bz % OG;
    int b  = bz / OG;
    int oc0 = og*16;
    int ox0 = blockIdx.x*32, oy0 = blockIdx.y*32;
    int gx0 = ox0 - PAD, gy0 = oy0 - PAD;
    const float* sb = src + b*CHW;
    ull acc[2][2][8];
    #pragma unroll
    for (int dy = 0; dy < 2; dy++)
    #pragma unroll
    for (int dx = 0; dx < 2; dx++)
    #pragma unroll
    for (int j = 0; j < 8; j++) acc[dy][dx][j] = 0ULL;

    #pragma unroll 1
    for (int ic0 = 0; ic0 < 64; ic0 += 4) {
        __syncthreads();
        for (int i = t; i < 4*TIW*TIW; i += 256) {
            int ic = i / (TIW*TIW);
            int r  = i - ic*TIW*TIW;
            int yy = r / TIW, xx = r - yy*TIW;
            int gy = gy0 + yy, gx = gx0 + xx;
            float v = 0.f;
            if (gy >= 0 && gy < HH && gx >= 0 && gx < WW)
                v = __ldg(sb + (ic0+ic)*HWSZ + gy*WW + gx);
            sIn[i] = v;
        }
        for (int i = t; i < 4*KK*8; i += 256) {
            int j  = i & 7;
            int rem = i >> 3;
            int k  = rem % KK;
            int ic = rem / KK;
            int oc = oc0 + 2*j;
            ull v = 0ULL;
            if (oc < OTOT)
                v = *(const ull*)(owT + (size_t)((ic0+ic)*KK + k)*OTOT + oc);
            sW[i] = v;
        }
        __syncthreads();
        #pragma unroll 1
        for (int ic = 0; ic < 4; ic++) {
            #pragma unroll 1
            for (int ky = 0; ky < K; ky++) {
                #pragma unroll
                for (int kx = 0; kx < K; kx++) {
                    ull v2[2][2];
                    #pragma unroll
                    for (int dy = 0; dy < 2; dy++)
                    #pragma unroll
                    for (int dx = 0; dx < 2; dx++) {
                        float f = sIn[ic*TIW*TIW + (2*ty+ky+dy)*TIW + 2*tx+kx+dx];
                        v2[dy][dx] = pack2(f, f);
                    }
                    const ull* wr = sW + (ic*KK + ky*K + kx)*8;
                    #pragma unroll
                    for (int j = 0; j < 8; j++) {
                        ull wv = wr[j];
                        acc[0][0][j] = fma2(v2[0][0], wv, acc[0][0][j]);
                        acc[0][1][j] = fma2(v2[0][1], wv, acc[0][1][j]);
                        acc[1][0][j] = fma2(v2[1][0], wv, acc[1][0][j]);
                        acc[1][1][j] = fma2(v2[1][1], wv, acc[1][1][j]);
                    }
                }
            }
        }
    }
    #pragma unroll
    for (int j = 0; j < 8; j++) {
        int oc = oc0 + 2*j;
        if (oc < OTOT) {
            float b0 = __ldg(bias + oc), b1 = __ldg(bias + oc + 1);
            #pragma unroll
            for (int dy = 0; dy < 2; dy++)
            #pragma unroll
            for (int dx = 0; dx < 2; dx++) {
                float lo, hi; unpack2(acc[dy][dx][j], lo, hi);
                int py = oy0 + 2*ty + dy, px = ox0 + 2*tx + dx;
                float* dp = dst + (size_t)b*OTOT*HWSZ + oc*HWSZ + py*WW + px;
                dp[0]    = lo + b0;
                dp[HWSZ] = hi + b1;
            }
        }
    }
}

// ---------- deformable conv v6: gather + HMMA f16-split, MANUAL fragment loads ----------
// Tile: 128 px (M) x 64 oc (N) x 64 c (K) per tap; fp32 acc across taps.
// A [128 rows][144B stride] hi/lo f16; B [64 rows][144B stride] hi/lo f16. No swizzle.
#define ASTR 144
#define SA_HI 0
#define SA_LO (128*ASTR)
#define SB_HI (2*128*ASTR)
#define SB_LO (2*128*ASTR + 64*ASTR)
#define D_SMEM (2*128*ASTR + 2*64*ASTR)   // 55296

template<int K, int PAD>
__global__ __launch_bounds__(256) void k_deform_mma(
    const float* __restrict__ src, const float* __restrict__ off,
    const __half* __restrict__ wbh, const __half* __restrict__ wbl,
    const float* __restrict__ bias, float* __restrict__ dst) {
    constexpr int KK = K*K;
    extern __shared__ char smem[];

    int t = threadIdx.x;
    int w = t >> 5, li = t & 31;
    int hw0 = blockIdx.x * 128;
    int b   = blockIdx.y;
    const float* srcb = src + b*CHW;
    const float* offb = off + (size_t)b*(2*KK)*HWSZ;

    // sampling mapping
    int spx = t & 127;
    int c0  = (t >> 7) * 32;
    int hw = hw0 + spx;
    int hh = hw / WW, xx = hw - hh*WW;

    // fragment lane indices
    int g  = li >> 2;       // groupID 0..7
    int tg = li & 3;        // threadID_in_group 0..3

    float acc[8][4];
    #pragma unroll
    for (int nt = 0; nt < 8; nt++)
    #pragma unroll
    for (int j = 0; j < 4; j++) acc[nt][j] = 0.f;

    float oy = __ldg(offb + hw);
    float ox = __ldg(offb + HWSZ + hw);

    #pragma unroll 1
    for (int k = 0; k < KK; k++) {
        // --- bilinear coords in regs ---
        float w0, w1, w2, w3;
        int   o0, o1, o2, o3;
        {
            int ki = k / K, kj = k - ki*K;
            float py = (float)(hh + ki - PAD) + oy;
            float px = (float)(xx + kj - PAD) + ox;
            float y0f = floorf(py), x0f = floorf(px);
            float wy = py - y0f, wx = px - x0f;
            int y0 = (int)y0f, x0 = (int)x0f;
            int y1 = y0 + 1, x1i = x0 + 1;
            float my0 = (y0  >= 0 && y0  < HH) ? 1.f : 0.f;
            float my1 = (y1  >= 0 && y1  < HH) ? 1.f : 0.f;
            float mx0 = (x0  >= 0 && x0  < WW) ? 1.f : 0.f;
            float mx1 = (x1i >= 0 && x1i < WW) ? 1.f : 0.f;
            int yc0 = min(max(y0, 0), HH-1), yc1 = min(max(y1, 0), HH-1);
            int xc0 = min(max(x0, 0), WW-1), xc1 = min(max(x1i, 0), WW-1);
            w0 = my0*mx0*(1.f-wy)*(1.f-wx);
            w1 = my0*mx1*(1.f-wy)*wx;
            w2 = my1*mx0*wy*(1.f-wx);
            w3 = my1*mx1*wy*wx;
            o0 = yc0*WW + xc0;  o1 = yc0*WW + xc1;
            o2 = yc1*WW + xc0;  o3 = yc1*WW + xc1;
        }
        // --- stage weights (pre-split f16; 16B chunks) ---
        {
            const uint4* gh = (const uint4*)(wbh + (size_t)k*4096);
            const uint4* gl = (const uint4*)(wbl + (size_t)k*4096);
            #pragma unroll
            for (int pp = 0; pp < 2; pp++) {
                int i = t + pp*256;               // 0..511 = 64 oc x 8 chunks
                int oc = i >> 3, cc = i & 7;
                uint32_t so = (uint32_t)(oc*ASTR + cc*16);
                *(uint4*)(smem + SB_HI + so) = __ldg(gh + i);
                *(uint4*)(smem + SB_LO + so) = __ldg(gl + i);
            }
        }
        // --- sample 32 channels for pixel spx, write f16 hi/lo pairs ---
        {
            #pragma unroll 2
            for (int i = 0; i < 16; i++) {
                int c = c0 + 2*i;
                const float* p0 = srcb + (size_t)c*HWSZ;
                const float* p1 = p0 + HWSZ;
                float v0 = __ldg(p0+o0)*w0 + __ldg(p0+o1)*w1 + __ldg(p0+o2)*w2 + __ldg(p0+o3)*w3;
                float v1 = __ldg(p1+o0)*w0 + __ldg(p1+o1)*w1 + __ldg(p1+o2)*w2 + __ldg(p1+o3)*w3;
                __half h0 = __float2half_rn(v0);
                __half h1 = __float2half_rn(v1);
                uint32_t hi = hfu(h0) | (hfu(h1) << 16);
                float r0 = v0 - __half2float(h0);
                float r1 = v1 - __half2float(h1);
                uint32_t lo = hfu(__float2half_rn(r0)) | (hfu(__float2half_rn(r1)) << 16);
                uint32_t so = (uint32_t)(spx*ASTR + c*2);
                *(uint32_t*)(smem + SA_HI + so) = hi;
                *(uint32_t*)(smem + SA_LO + so) = lo;
            }
        }
        __syncthreads();
        // --- prefetch next tap offsets ---
        if (k + 1 < KK) {
            oy = __ldg(offb + (size_t)(2*k+2)*HWSZ + hw);
            ox = __ldg(offb + (size_t)(2*k+3)*HWSZ + hw);
        }
        // --- HMMA: manual fragment loads per the m16n8k16 fragment tables ---
        #pragma unroll
        for (int ks = 0; ks < 4; ks++) {
            uint32_t aRow0 = (uint32_t)((w*16 + g)*ASTR + ks*32 + tg*4);
            uint32_t aRow1 = aRow0 + 8*ASTR;
            uint32_t ah0 = *(const uint32_t*)(smem + SA_HI + aRow0);
            uint32_t ah1 = *(const uint32_t*)(smem + SA_HI + aRow1);
            uint32_t ah2 = *(const uint32_t*)(smem + SA_HI + aRow0 + 16);
            uint32_t ah3 = *(const uint32_t*)(smem + SA_HI + aRow1 + 16);
            uint32_t al0 = *(const uint32_t*)(smem + SA_LO + aRow0);
            uint32_t al1 = *(const uint32_t*)(smem + SA_LO + aRow1);
            uint32_t al2 = *(const uint32_t*)(smem + SA_LO + aRow0 + 16);
            uint32_t al3 = *(const uint32_t*)(smem + SA_LO + aRow1 + 16);
            #pragma unroll
            for (int q = 0; q < 4; q++) {
                uint32_t bRowA = (uint32_t)((q*16 + g)*ASTR + ks*32 + tg*4);
                uint32_t bRowB = bRowA + 8*ASTR;
                uint32_t bhA0 = *(const uint32_t*)(smem + SB_HI + bRowA);
                uint32_t bhA1 = *(const uint32_t*)(smem + SB_HI + bRowA + 16);
                uint32_t bhB0 = *(const uint32_t*)(smem + SB_HI + bRowB);
                uint32_t bhB1 = *(const uint32_t*)(smem + SB_HI + bRowB + 16);
                uint32_t blA0 = *(const uint32_t*)(smem + SB_LO + bRowA);
                uint32_t blA1 = *(const uint32_t*)(smem + SB_LO + bRowA + 16);
                uint32_t blB0 = *(const uint32_t*)(smem + SB_LO + bRowB);
                uint32_t blB1 = *(const uint32_t*)(smem + SB_LO + bRowB + 16);
                mma_f16(acc[2*q],   ah0, ah1, ah2, ah3, bhA0, bhA1);
                mma_f16(acc[2*q+1], ah0, ah1, ah2, ah3, bhB0, bhB1);
                mma_f16(acc[2*q],   ah0, ah1, ah2, ah3, blA0, blA1);
                mma_f16(acc[2*q+1], ah0, ah1, ah2, ah3, blB0, blB1);
                mma_f16(acc[2*q],   al0, al1, al2, al3, bhA0, bhA1);
                mma_f16(acc[2*q+1], al0, al1, al2, al3, bhB0, bhB1);
            }
        }
        __syncthreads();
    }
    // --- epilogue ---
    {
        float* db = dst + (size_t)b*CHW + hw0;
        int pxr = w*16 + g;
        #pragma unroll
        for (int nt = 0; nt < 8; nt++) {
            int oc = nt*8 + tg*2;
            float b0 = __ldg(bias + oc), b1 = __ldg(bias + oc + 1);
            db[(size_t)oc*HWSZ + pxr]           = acc[nt][0] + b0;
            db[(size_t)(oc+1)*HWSZ + pxr]       = acc[nt][1] + b1;
            db[(size_t)oc*HWSZ + pxr + 8]       = acc[nt][2] + b0;
            db[(size_t)(oc+1)*HWSZ + pxr + 8]   = acc[nt][3] + b1;
        }
    }
}

// ---------- final: (x1+x2) @ w_out + b_out + residual ----------
__global__ __launch_bounds__(128) void k_final(
    const float* __restrict__ t1, const float* __restrict__ t2,
    const float* __restrict__ xres, const float* __restrict__ wpk,
    const float* __restrict__ bout, float* __restrict__ out) {
    __shared__ ull sW[2048];
    __shared__ float sB[64];
    int t = threadIdx.x;
    const ull* wp = (const ull*)wpk;
    #pragma unroll
    for (int i = 0; i < 16; i++) sW[t + i*128] = wp[t + i*128];
    if (t < 64) sB[t] = bout[t];
    __syncthreads();
    int pix = blockIdx.x*128 + t;
    int b = pix / HWSZ, hw = pix - b*HWSZ;
    const float* p1 = t1 + b*CHW + hw;
    const float* p2 = t2 + b*CHW + hw;
    ull acc[32];
    #pragma unroll
    for (int j = 0; j < 32; j++) acc[j] = pack2(sB[2*j], sB[2*j+1]);
    #pragma unroll 1
    for (int c = 0; c < 64; c++) {
        float v = __ldg(p1 + c*HWSZ) + __ldg(p2 + c*HWSZ);
        ull vb = pack2(v, v);
        const ull* wc = sW + c*32;
        #pragma unroll
        for (int j = 0; j < 32; j++) acc[j] = fma2(vb, wc[j], acc[j]);
    }
    const float* xr = xres + b*CHW + hw;
    float* op = out + b*CHW + hw;
    #pragma unroll
    for (int j = 0; j < 32; j++) {
        float lo, hi; unpack2(acc[j], lo, hi);
        op[(2*j)*HWSZ]   = lo + __ldg(xr + (2*j)*HWSZ);
        op[(2*j+1)*HWSZ] = hi + __ldg(xr + (2*j+1)*HWSZ);
    }
}

extern "C" void kernel_launch(void* const* d_in, const int* in_sizes, int n_in,
                              void* d_out, int out_size) {
    const float* x    = (const float*)d_in[0];
    const float* lnw  = (const float*)d_in[1];
    const float* lnb  = (const float*)d_in[2];
    const float* w_in = (const float*)d_in[3];
    const float* b_in = (const float*)d_in[4];
    const float* w_out= (const float*)d_in[5];
    const float* b_out= (const float*)d_in[6];
    const float* dw1  = (const float*)d_in[7];
    const float* db1  = (const float*)d_in[8];
    const float* dw2  = (const float*)d_in[9];
    const float* db2  = (const float*)d_in[10];
    const float* dw3  = (const float*)d_in[11];
    const float* db3  = (const float*)d_in[12];
    const float* ow1  = (const float*)d_in[13];
    const float* ob1  = (const float*)d_in[14];
    const float* ow2  = (const float*)d_in[15];
    const float* ob2  = (const float*)d_in[16];
    const float* ow3  = (const float*)d_in[17];
    const float* ob3  = (const float*)d_in[18];
    float* out = (float*)d_out;

    float *x1, *x2, *tmp, *offb, *wT, *wpi, *wpo;
    __half *wbh, *wbl;
    cudaGetSymbolAddress((void**)&x1,  g_x1);
    cudaGetSymbolAddress((void**)&x2,  g_x2);
    cudaGetSymbolAddress((void**)&tmp, g_tmp);
    cudaGetSymbolAddress((void**)&offb,g_off);
    cudaGetSymbolAddress((void**)&wT,  g_wT);
    cudaGetSymbolAddress((void**)&wbh, g_whfh);
    cudaGetSymbolAddress((void**)&wbl, g_whfl);
    cudaGetSymbolAddress((void**)&wpi, g_wpk_in);
    cudaGetSymbolAddress((void**)&wpo, g_wpk_out);

    cudaFuncSetAttribute(k_deform_mma<7,3>, cudaFuncAttributeMaxDynamicSharedMemorySize, D_SMEM);
    cudaFuncSetAttribute(k_deform_mma<5,2>, cudaFuncAttributeMaxDynamicSharedMemorySize, D_SMEM);
    cudaFuncSetAttribute(k_deform_mma<3,1>, cudaFuncAttributeMaxDynamicSharedMemorySize, D_SMEM);

    const int WD1 = 0, WD2 = 49*4096, WD3 = 74*4096;
    const int WO1 = 0;
    const int WO2 = WO1 + 64*25*98;
    const int WO3 = WO2 + 64*25*50;

    // ncu profiles launch index 3 -> dummy deform there (output fully overwritten later)
    k_tr_lin<<<(64*128+255)/256, 256>>>(w_in,  wpi, 128, 64);                          // 0
    k_tr_deform_hf<<<(49*4096+255)/256, 256>>>(dw1, wbh+WD1, wbl+WD1, 49);             // 1
    k_tr_conv<<<(64*25*98+255)/256, 256>>>(ow1, wT+WO1, 98, 25);                       // 2
    k_deform_mma<7,3><<<dim3(148,1), 256, D_SMEM>>>(x1, offb, wbh+WD1, wbl+WD1, db1, tmp); // 3 <- profiled (dummy)
    k_ln_win<<<BB*HWSZ/128, 128>>>(x, lnw, lnb, wpi, b_in, x1, x2);                    // 4
    k_conv<5,98><<<dim3(6,6,4*7), 256>>>(x1,  wT+WO1, ob1, offb);                      // 5
    k_deform_mma<7,3><<<dim3(288,4), 256, D_SMEM>>>(x1, offb, wbh+WD1, wbl+WD1, db1, tmp); // 6
    k_tr_lin<<<(64*64+255)/256, 256>>>(w_out, wpo, 64, 64);                            // 7 <- RESTORED (the R10-R13 bug)
    k_tr_conv<<<(64*25*50+255)/256, 256>>>(ow2, wT+WO2, 50, 25);                       // 8
    k_conv<5,50><<<dim3(6,6,4*4), 256>>>(tmp, wT+WO2, ob2, offb);                      // 9
    k_tr_deform_hf<<<(25*4096+255)/256, 256>>>(dw2, wbh+WD2, wbl+WD2, 25);             // 10
    k_deform_mma<5,2><<<dim3(288,4), 256, D_SMEM>>>(tmp, offb, wbh+WD2, wbl+WD2, db2, x1); // 11
    k_tr_conv<<<(64*9*18+255)/256, 256>>>(ow3, wT+WO3, 18, 9);                         // 12
    k_conv<3,18><<<dim3(6,6,4*2), 256>>>(x1,  wT+WO3, ob3, offb);                      // 13
    k_tr_deform_hf<<<( 9*4096+255)/256, 256>>>(dw3, wbh+WD3, wbl+WD3, 9);              // 14
    k_deform_mma<3,1><<<dim3(288,4), 256, D_SMEM>>>(x1, offb, wbh+WD3, wbl+WD3, db3, tmp); // 15
    k_final<<<BB*HWSZ/128, 128>>>(tmp, x2, x, wpo, b_out, out);                        // 16
}